// round 8
// baseline (speedup 1.0000x reference)
#include <cuda_runtime.h>
#include <cuda_bf16.h>

// PrototypeLoss: out = mean_i ||features[i] - prototypes[labels[i]]||^2
// N=131072, D=512, C=1000. Pure HBM-streaming reduction (~257 MB read).
//
// inputs identified by element count (robust to ordering):
//   features f32 [N,D]   = 67108864 elems
//   labels   int [N]     = 131072 elems  (dtype sniffed on device: i32 vs i64)
//   protos   f32 [C,D]   = 512000 elems
// output: f32 [1,1]

#define N_ROWS 131072
#define N_CLASSES 1000
#define D_VEC  128          // D/4 float4 per row
#define GRID_BLOCKS (148 * 16)
#define BLOCK_THREADS 256
#define WARPS_TOTAL ((GRID_BLOCKS * BLOCK_THREADS) >> 5)

__device__ double g_acc;
__device__ int    g_lbl_is64;

// Decide label dtype on-device: for int64 labels in [0,1000), the high 32-bit
// word of each entry is 0. Check the odd 32-bit words of the first 64 entries
// (stays within the first N*4 bytes, safe for either dtype).
__global__ void sniff_and_zero_kernel(const unsigned* __restrict__ lw) {
    unsigned o = 0;
    #pragma unroll
    for (int i = 1; i < 128; i += 2) o |= lw[i];
    g_lbl_is64 = (o == 0u) ? 1 : 0;
    g_acc = 0.0;
}

__device__ __forceinline__ float row_dist_partial(const float4* __restrict__ f,
                                                  const float4* __restrict__ p,
                                                  int lane) {
    float acc = 0.0f;
    #pragma unroll
    for (int j = 0; j < 4; j++) {
        const int idx = lane + j * 32;
        float4 a = f[idx];
        float4 b = p[idx];
        float dx = a.x - b.x;
        float dy = a.y - b.y;
        float dz = a.z - b.z;
        float dw = a.w - b.w;
        acc = fmaf(dx, dx, acc);
        acc = fmaf(dy, dy, acc);
        acc = fmaf(dz, dz, acc);
        acc = fmaf(dw, dw, acc);
    }
    return acc;
}

__global__ __launch_bounds__(BLOCK_THREADS)
void proto_loss_kernel(const float4* __restrict__ feat,
                       const void* __restrict__ labels_raw,
                       const float4* __restrict__ protos) {
    const int lane   = threadIdx.x & 31;
    const int wid    = threadIdx.x >> 5;
    const int gwarp  = (blockIdx.x * BLOCK_THREADS + threadIdx.x) >> 5;

    const int is64 = g_lbl_is64;
    const int*       l32 = (const int*)labels_raw;
    const long long* l64 = (const long long*)labels_raw;

    float acc = 0.0f;

    // Two rows in flight per warp iteration -> higher MLP to hide DRAM latency.
    // N_ROWS / WARPS_TOTAL = 131072 / 18944 is not integral, so guard row1.
    for (int row = gwarp; row < N_ROWS; row += 2 * WARPS_TOTAL) {
        const int row0 = row;
        const int row1 = row + WARPS_TOTAL;

        int lbl0 = is64 ? (int)l64[row0] : l32[row0];
        lbl0 = (lbl0 < 0) ? 0 : (lbl0 >= N_CLASSES ? N_CLASSES - 1 : lbl0);
        const float4* f0 = feat   + (size_t)row0 * D_VEC;
        const float4* p0 = protos + (size_t)lbl0 * D_VEC;

        if (row1 < N_ROWS) {
            int lbl1 = is64 ? (int)l64[row1] : l32[row1];
            lbl1 = (lbl1 < 0) ? 0 : (lbl1 >= N_CLASSES ? N_CLASSES - 1 : lbl1);
            const float4* f1 = feat   + (size_t)row1 * D_VEC;
            const float4* p1 = protos + (size_t)lbl1 * D_VEC;
            acc += row_dist_partial(f0, p0, lane);
            acc += row_dist_partial(f1, p1, lane);
        } else {
            acc += row_dist_partial(f0, p0, lane);
        }
    }

    // warp reduce
    #pragma unroll
    for (int off = 16; off; off >>= 1)
        acc += __shfl_xor_sync(0xFFFFFFFFu, acc, off);

    __shared__ float ssum[BLOCK_THREADS / 32];
    if (lane == 0) ssum[wid] = acc;
    __syncthreads();

    if (wid == 0) {
        float v = (lane < (BLOCK_THREADS / 32)) ? ssum[lane] : 0.0f;
        #pragma unroll
        for (int off = 16; off; off >>= 1)
            v += __shfl_xor_sync(0xFFFFFFFFu, v, off);
        if (lane == 0)
            atomicAdd(&g_acc, (double)v);
    }
}

__global__ void finalize_kernel(float* __restrict__ out) {
    out[0] = (float)(g_acc * (1.0 / (double)N_ROWS));
}

extern "C" void kernel_launch(void* const* d_in, const int* in_sizes, int n_in,
                              void* d_out, int out_size) {
    // Identify inputs by element count (robust against metadata ordering).
    const float4* feat   = 0;
    const void*   labels = 0;
    const float4* protos = 0;
    for (int i = 0; i < n_in; i++) {
        if (in_sizes[i] == N_ROWS * 512)          feat   = (const float4*)d_in[i];
        else if (in_sizes[i] == N_CLASSES * 512)  protos = (const float4*)d_in[i];
        else                                      labels = d_in[i];
    }
    float* out = (float*)d_out;

    sniff_and_zero_kernel<<<1, 1>>>((const unsigned*)labels);
    proto_loss_kernel<<<GRID_BLOCKS, BLOCK_THREADS>>>(feat, labels, protos);
    finalize_kernel<<<1, 1>>>(out);
}